// round 4
// baseline (speedup 1.0000x reference)
#include <cuda_runtime.h>
#include <math.h>

#define B_ 4
#define S_ 2048
#define D_ 1024
#define F_ 4096

// ---------------- scratch (device globals: allocation-free) ----------------
__device__ float g_scores[(size_t)B_ * S_ * S_];   //  64 MB
__device__ float g_attn  [(size_t)B_ * S_ * D_];   //  32 MB
__device__ float g_x     [(size_t)B_ * S_ * D_];   //  32 MB
__device__ float g_y     [(size_t)B_ * S_ * F_];   // 128 MB
__device__ float g_f     [(size_t)B_ * S_ * D_];   //  32 MB

// ---------------- helpers ----------------
__device__ __forceinline__ unsigned long long dup2(float x) {
    unsigned long long r;
    asm("mov.b64 %0, {%1, %1};" : "=l"(r) : "f"(x));
    return r;
}
__device__ __forceinline__ void ffma2(unsigned long long& d,
                                      unsigned long long a,
                                      unsigned long long b) {
    // packed fp32x2 FMA (sm_103a FFMA2): 2x scalar FFMA throughput
    asm("fma.rn.f32x2 %0, %1, %2, %0;" : "+l"(d) : "l"(a), "l"(b));
}
__device__ __forceinline__ float2 unpack2(unsigned long long v) {
    float2 r;
    asm("mov.b64 {%0, %1}, %2;" : "=f"(r.x), "=f"(r.y) : "l"(v));
    return r;
}
__device__ __forceinline__ float gelu_exact(float x) {
    return 0.5f * x * (1.0f + erff(x * 0.7071067811865476f));
}
__device__ __forceinline__ float warpSum(float v) {
#pragma unroll
    for (int o = 16; o; o >>= 1) v += __shfl_xor_sync(0xffffffffu, v, o);
    return v;
}
__device__ __forceinline__ float warpMax(float v) {
#pragma unroll
    for (int o = 16; o; o >>= 1) v = fmaxf(v, __shfl_xor_sync(0xffffffffu, v, o));
    return v;
}

// ---------------- tiled SGEMM: C = epi(A @ B) ----------------
// A: [M,K] row-major. B: BT ? [N,K] row-major (i.e. A@B^T) : [K,N] row-major.
// 128x128 tile, BK=16, 256 threads, 8x8 micro-tile, f32x2 packed FMA.
// EPI: 0 -> C = acc*alpha ; 1 -> C = gelu(acc + bias[col]) ; 2 -> C = acc + bias[col]
template <bool BT, int EPI>
__global__ void __launch_bounds__(256, 2)
gemm_kernel(const float* __restrict__ A, const float* __restrict__ B,
            float* __restrict__ C, int M, int N, int K,
            size_t sA, size_t sB, size_t sC,
            const float* __restrict__ bias, float alpha) {
    __shared__ float As[16][132];
    __shared__ float Bs[16][132];

    A += (size_t)blockIdx.z * sA;
    B += (size_t)blockIdx.z * sB;
    C += (size_t)blockIdx.z * sC;

    const int tid = threadIdx.x;
    const int tx = tid & 15;        // 0..15 -> N micro
    const int ty = tid >> 4;        // 0..15 -> M micro

    // global->smem load mapping
    const int lrow = tid >> 1;            // 0..127
    const int lcol = (tid & 1) << 3;      // 0 or 8
    const int bk   = tid >> 4;            // 0..15  (NN B)
    const int bn   = (tid & 15) << 3;     // 0..120 (NN B)

    const float* Aptr = A + (size_t)(blockIdx.y * 128 + lrow) * K + lcol;
    const float* Bptr = BT ? (B + (size_t)(blockIdx.x * 128 + lrow) * K + lcol)
                           : (B + (size_t)bk * N + blockIdx.x * 128 + bn);

    unsigned long long acc[4][8];
#pragma unroll
    for (int i = 0; i < 4; i++)
#pragma unroll
        for (int j = 0; j < 8; j++) acc[i][j] = 0ULL;

    for (int k0 = 0; k0 < K; k0 += 16) {
        // ---- load tile to smem ----
        float4 a0 = *(const float4*)Aptr;
        float4 a1 = *(const float4*)(Aptr + 4);
        As[lcol + 0][lrow] = a0.x; As[lcol + 1][lrow] = a0.y;
        As[lcol + 2][lrow] = a0.z; As[lcol + 3][lrow] = a0.w;
        As[lcol + 4][lrow] = a1.x; As[lcol + 5][lrow] = a1.y;
        As[lcol + 6][lrow] = a1.z; As[lcol + 7][lrow] = a1.w;
        if (BT) {
            float4 b0 = *(const float4*)Bptr;
            float4 b1 = *(const float4*)(Bptr + 4);
            Bs[lcol + 0][lrow] = b0.x; Bs[lcol + 1][lrow] = b0.y;
            Bs[lcol + 2][lrow] = b0.z; Bs[lcol + 3][lrow] = b0.w;
            Bs[lcol + 4][lrow] = b1.x; Bs[lcol + 5][lrow] = b1.y;
            Bs[lcol + 6][lrow] = b1.z; Bs[lcol + 7][lrow] = b1.w;
        } else {
            float4 b0 = *(const float4*)Bptr;
            float4 b1 = *(const float4*)(Bptr + 4);
            *(float4*)&Bs[bk][bn]     = b0;
            *(float4*)&Bs[bk][bn + 4] = b1;
        }
        Aptr += 16;
        if (BT) Bptr += 16; else Bptr += (size_t)16 * N;
        __syncthreads();

        // ---- compute ----
#pragma unroll
        for (int k = 0; k < 16; k++) {
            float4 fa0 = *(const float4*)(&As[k][ty * 4]);
            float4 fa1 = *(const float4*)(&As[k][64 + ty * 4]);
            float4 fb0 = *(const float4*)(&Bs[k][tx * 4]);
            float4 fb1 = *(const float4*)(&Bs[k][64 + tx * 4]);
            unsigned long long ap[4];
            ap[0] = ((const unsigned long long*)&fa0)[0];
            ap[1] = ((const unsigned long long*)&fa0)[1];
            ap[2] = ((const unsigned long long*)&fa1)[0];
            ap[3] = ((const unsigned long long*)&fa1)[1];
            unsigned long long bp[8];
            bp[0] = dup2(fb0.x); bp[1] = dup2(fb0.y);
            bp[2] = dup2(fb0.z); bp[3] = dup2(fb0.w);
            bp[4] = dup2(fb1.x); bp[5] = dup2(fb1.y);
            bp[6] = dup2(fb1.z); bp[7] = dup2(fb1.w);
#pragma unroll
            for (int i = 0; i < 4; i++)
#pragma unroll
                for (int j = 0; j < 8; j++) ffma2(acc[i][j], ap[i], bp[j]);
        }
        __syncthreads();
    }

    // ---- epilogue ----
    float c[8][8];
#pragma unroll
    for (int i = 0; i < 4; i++)
#pragma unroll
        for (int j = 0; j < 8; j++) {
            float2 t = unpack2(acc[i][j]);
            c[2 * i][j] = t.x; c[2 * i + 1][j] = t.y;
        }

    const int gr = blockIdx.y * 128 + ty * 4;
    const int gc = blockIdx.x * 128 + tx * 4;
#pragma unroll
    for (int ih = 0; ih < 2; ih++)
#pragma unroll
        for (int ii = 0; ii < 4; ii++) {
            const int row = gr + ih * 64 + ii;
            const int ci  = ih * 4 + ii;
#pragma unroll
            for (int jh = 0; jh < 2; jh++) {
                const int col = gc + jh * 64;
                float t0 = c[ci][jh * 4 + 0], t1 = c[ci][jh * 4 + 1];
                float t2 = c[ci][jh * 4 + 2], t3 = c[ci][jh * 4 + 3];
                if (EPI == 0) {
                    t0 *= alpha; t1 *= alpha; t2 *= alpha; t3 *= alpha;
                } else {
                    const float4 bv = *(const float4*)(bias + col);
                    t0 += bv.x; t1 += bv.y; t2 += bv.z; t3 += bv.w;
                    if (EPI == 1) {
                        t0 = gelu_exact(t0); t1 = gelu_exact(t1);
                        t2 = gelu_exact(t2); t3 = gelu_exact(t3);
                    }
                }
                *(float4*)(C + (size_t)row * N + col) = make_float4(t0, t1, t2, t3);
            }
        }
}

// ---------------- softmax over rows of [B*S, S] with additive mask[b, k] ----
__global__ void softmax_kernel(float* __restrict__ P, const float* __restrict__ mask) {
    __shared__ float sh[8];
    const int row = blockIdx.x;           // 0..B*S-1
    const int b   = row >> 11;            // S_ = 2048
    float* p = P + (size_t)row * S_;
    const float* m = mask + (size_t)b * S_;
    const int tid = threadIdx.x;          // 256 threads, 8 elems each

    float v[8];
    float mx = -1e30f;
#pragma unroll
    for (int i = 0; i < 8; i++) {
        const int idx = tid + (i << 8);
        v[i] = p[idx] + m[idx];
        mx = fmaxf(mx, v[i]);
    }
    mx = warpMax(mx);
    if ((tid & 31) == 0) sh[tid >> 5] = mx;
    __syncthreads();
    mx = sh[0];
#pragma unroll
    for (int j = 1; j < 8; j++) mx = fmaxf(mx, sh[j]);

    float s = 0.f;
#pragma unroll
    for (int i = 0; i < 8; i++) { v[i] = expf(v[i] - mx); s += v[i]; }
    s = warpSum(s);
    __syncthreads();
    if ((tid & 31) == 0) sh[tid >> 5] = s;
    __syncthreads();
    s = 0.f;
#pragma unroll
    for (int j = 0; j < 8; j++) s += sh[j];
    const float inv = 1.0f / s;
#pragma unroll
    for (int i = 0; i < 8; i++) p[tid + (i << 8)] = v[i] * inv;
}

// ---------------- out = LayerNorm(X + Y) * gamma + beta, rows of D_=1024 ----
__global__ void add_ln_kernel(const float* __restrict__ X, const float* __restrict__ Y,
                              const float* __restrict__ gamma, const float* __restrict__ beta,
                              float* __restrict__ O) {
    __shared__ float shs[8], shq[8];
    const int row = blockIdx.x;
    const int tid = threadIdx.x;          // 256 threads * 4 = 1024
    const size_t base = (size_t)row * D_ + tid * 4;

    const float4 a = *(const float4*)(X + base);
    const float4 b = *(const float4*)(Y + base);
    const float v0 = a.x + b.x, v1 = a.y + b.y, v2 = a.z + b.z, v3 = a.w + b.w;

    float s = v0 + v1 + v2 + v3;
    float q = v0 * v0 + v1 * v1 + v2 * v2 + v3 * v3;
    s = warpSum(s); q = warpSum(q);
    if ((tid & 31) == 0) { shs[tid >> 5] = s; shq[tid >> 5] = q; }
    __syncthreads();
    s = 0.f; q = 0.f;
#pragma unroll
    for (int j = 0; j < 8; j++) { s += shs[j]; q += shq[j]; }
    const float mean = s * (1.0f / D_);
    const float var  = q * (1.0f / D_) - mean * mean;
    const float rstd = rsqrtf(var + 1e-5f);

    const float4 g  = *(const float4*)(gamma + tid * 4);
    const float4 bt = *(const float4*)(beta  + tid * 4);
    float4 o;
    o.x = (v0 - mean) * rstd * g.x + bt.x;
    o.y = (v1 - mean) * rstd * g.y + bt.y;
    o.z = (v2 - mean) * rstd * g.z + bt.z;
    o.w = (v3 - mean) * rstd * g.w + bt.w;
    *(float4*)(O + base) = o;
}

// ---------------- launch ----------------
extern "C" void kernel_launch(void* const* d_in, const int* in_sizes, int n_in,
                              void* d_out, int out_size) {
    const float* h   = (const float*)d_in[0];
    const float* msk = (const float*)d_in[1];
    const float* w1  = (const float*)d_in[2];
    const float* b1  = (const float*)d_in[3];
    const float* w2  = (const float*)d_in[4];
    const float* b2  = (const float*)d_in[5];
    const float* g1  = (const float*)d_in[6];
    const float* be1 = (const float*)d_in[7];
    const float* g2  = (const float*)d_in[8];
    const float* be2 = (const float*)d_in[9];
    float* out = (float*)d_out;

    float *scores, *attn, *x, *y, *f;
    cudaGetSymbolAddress((void**)&scores, g_scores);
    cudaGetSymbolAddress((void**)&attn,   g_attn);
    cudaGetSymbolAddress((void**)&x,      g_x);
    cudaGetSymbolAddress((void**)&y,      g_y);
    cudaGetSymbolAddress((void**)&f,      g_f);

    // 1) scores = (h @ h^T) / sqrt(D)   [B,S,S]
    gemm_kernel<true, 0><<<dim3(S_ / 128, S_ / 128, B_), 256>>>(
        h, h, scores, S_, S_, D_,
        (size_t)S_ * D_, (size_t)S_ * D_, (size_t)S_ * S_, nullptr, 0.03125f);

    // 2) probs = softmax(scores + mask)   (in place)
    softmax_kernel<<<B_ * S_, 256>>>(scores, msk);

    // 3) attn = probs @ h   [B,S,D]
    gemm_kernel<false, 0><<<dim3(D_ / 128, S_ / 128, B_), 256>>>(
        scores, h, attn, S_, D_, S_,
        (size_t)S_ * S_, (size_t)S_ * D_, (size_t)S_ * D_, nullptr, 1.0f);

    // 4) x = LN1(h + attn)
    add_ln_kernel<<<B_ * S_, 256>>>(h, attn, g1, be1, x);

    // 5) y = gelu(x @ w1 + b1)   [B*S, F]
    gemm_kernel<false, 1><<<dim3(F_ / 128, (B_ * S_) / 128, 1), 256>>>(
        x, w1, y, B_ * S_, F_, D_, 0, 0, 0, b1, 1.0f);

    // 6) f = y @ w2 + b2   [B*S, D]
    gemm_kernel<false, 2><<<dim3(D_ / 128, (B_ * S_) / 128, 1), 256>>>(
        y, w2, f, B_ * S_, D_, F_, 0, 0, 0, b2, 1.0f);

    // 7) out = LN2(x + f)
    add_ln_kernel<<<B_ * S_, 256>>>(x, f, g2, be2, out);
}

// round 5
// speedup vs baseline: 1.0017x; 1.0017x over previous
#include <cuda_runtime.h>
#include <math.h>

#define B_ 4
#define S_ 2048
#define D_ 1024
#define F_ 4096

// ---------------- scratch (device globals: allocation-free) ----------------
__device__ float g_scores[(size_t)B_ * S_ * S_];   //  64 MB
__device__ float g_attn  [(size_t)B_ * S_ * D_];   //  32 MB
__device__ float g_x     [(size_t)B_ * S_ * D_];   //  32 MB
__device__ float g_y     [(size_t)B_ * S_ * F_];   // 128 MB
__device__ float g_f     [(size_t)B_ * S_ * D_];   //  32 MB

// ---------------- helpers ----------------
__device__ __forceinline__ unsigned long long dup2(float x) {
    unsigned long long r;
    asm("mov.b64 %0, {%1, %1};" : "=l"(r) : "f"(x));
    return r;
}
__device__ __forceinline__ void ffma2(unsigned long long& d,
                                      unsigned long long a,
                                      unsigned long long b) {
    // packed fp32x2 FMA (sm_103a FFMA2): 2x scalar FFMA throughput
    asm("fma.rn.f32x2 %0, %1, %2, %0;" : "+l"(d) : "l"(a), "l"(b));
}
__device__ __forceinline__ float2 unpack2(unsigned long long v) {
    float2 r;
    asm("mov.b64 {%0, %1}, %2;" : "=f"(r.x), "=f"(r.y) : "l"(v));
    return r;
}
__device__ __forceinline__ float gelu_exact(float x) {
    return 0.5f * x * (1.0f + erff(x * 0.7071067811865476f));
}
__device__ __forceinline__ float warpSum(float v) {
#pragma unroll
    for (int o = 16; o; o >>= 1) v += __shfl_xor_sync(0xffffffffu, v, o);
    return v;
}
__device__ __forceinline__ float warpMax(float v) {
#pragma unroll
    for (int o = 16; o; o >>= 1) v = fmaxf(v, __shfl_xor_sync(0xffffffffu, v, o));
    return v;
}

// ---------------- tiled SGEMM: C = epi(A @ B) ----------------
// A: [M,K] row-major. B: BT ? [N,K] row-major (i.e. A@B^T) : [K,N] row-major.
// 128x128 tile, BK=16, 256 threads, 8x8 micro-tile, f32x2 packed FMA.
// EPI: 0 -> C = acc*alpha ; 1 -> C = gelu(acc + bias[col]) ; 2 -> C = acc + bias[col]
template <bool BT, int EPI>
__global__ void __launch_bounds__(256, 2)
gemm_kernel(const float* __restrict__ A, const float* __restrict__ B,
            float* __restrict__ C, int M, int N, int K,
            size_t sA, size_t sB, size_t sC,
            const float* __restrict__ bias, float alpha) {
    __shared__ float As[16][132];
    __shared__ float Bs[16][132];

    A += (size_t)blockIdx.z * sA;
    B += (size_t)blockIdx.z * sB;
    C += (size_t)blockIdx.z * sC;

    const int tid = threadIdx.x;
    const int tx = tid & 15;        // 0..15 -> N micro
    const int ty = tid >> 4;        // 0..15 -> M micro

    // global->smem load mapping
    const int lrow = tid >> 1;            // 0..127
    const int lcol = (tid & 1) << 3;      // 0 or 8
    const int bk   = tid >> 4;            // 0..15  (NN B)
    const int bn   = (tid & 15) << 3;     // 0..120 (NN B)

    const float* Aptr = A + (size_t)(blockIdx.y * 128 + lrow) * K + lcol;
    const float* Bptr = BT ? (B + (size_t)(blockIdx.x * 128 + lrow) * K + lcol)
                           : (B + (size_t)bk * N + blockIdx.x * 128 + bn);

    unsigned long long acc[4][8];
#pragma unroll
    for (int i = 0; i < 4; i++)
#pragma unroll
        for (int j = 0; j < 8; j++) acc[i][j] = 0ULL;

    for (int k0 = 0; k0 < K; k0 += 16) {
        // ---- load tile to smem ----
        float4 a0 = *(const float4*)Aptr;
        float4 a1 = *(const float4*)(Aptr + 4);
        As[lcol + 0][lrow] = a0.x; As[lcol + 1][lrow] = a0.y;
        As[lcol + 2][lrow] = a0.z; As[lcol + 3][lrow] = a0.w;
        As[lcol + 4][lrow] = a1.x; As[lcol + 5][lrow] = a1.y;
        As[lcol + 6][lrow] = a1.z; As[lcol + 7][lrow] = a1.w;
        if (BT) {
            float4 b0 = *(const float4*)Bptr;
            float4 b1 = *(const float4*)(Bptr + 4);
            Bs[lcol + 0][lrow] = b0.x; Bs[lcol + 1][lrow] = b0.y;
            Bs[lcol + 2][lrow] = b0.z; Bs[lcol + 3][lrow] = b0.w;
            Bs[lcol + 4][lrow] = b1.x; Bs[lcol + 5][lrow] = b1.y;
            Bs[lcol + 6][lrow] = b1.z; Bs[lcol + 7][lrow] = b1.w;
        } else {
            float4 b0 = *(const float4*)Bptr;
            float4 b1 = *(const float4*)(Bptr + 4);
            *(float4*)&Bs[bk][bn]     = b0;
            *(float4*)&Bs[bk][bn + 4] = b1;
        }
        Aptr += 16;
        if (BT) Bptr += 16; else Bptr += (size_t)16 * N;
        __syncthreads();

        // ---- compute ----
#pragma unroll
        for (int k = 0; k < 16; k++) {
            float4 fa0 = *(const float4*)(&As[k][ty * 4]);
            float4 fa1 = *(const float4*)(&As[k][64 + ty * 4]);
            float4 fb0 = *(const float4*)(&Bs[k][tx * 4]);
            float4 fb1 = *(const float4*)(&Bs[k][64 + tx * 4]);
            unsigned long long ap[4];
            ap[0] = ((const unsigned long long*)&fa0)[0];
            ap[1] = ((const unsigned long long*)&fa0)[1];
            ap[2] = ((const unsigned long long*)&fa1)[0];
            ap[3] = ((const unsigned long long*)&fa1)[1];
            unsigned long long bp[8];
            bp[0] = dup2(fb0.x); bp[1] = dup2(fb0.y);
            bp[2] = dup2(fb0.z); bp[3] = dup2(fb0.w);
            bp[4] = dup2(fb1.x); bp[5] = dup2(fb1.y);
            bp[6] = dup2(fb1.z); bp[7] = dup2(fb1.w);
#pragma unroll
            for (int i = 0; i < 4; i++)
#pragma unroll
                for (int j = 0; j < 8; j++) ffma2(acc[i][j], ap[i], bp[j]);
        }
        __syncthreads();
    }

    // ---- epilogue ----
    float c[8][8];
#pragma unroll
    for (int i = 0; i < 4; i++)
#pragma unroll
        for (int j = 0; j < 8; j++) {
            float2 t = unpack2(acc[i][j]);
            c[2 * i][j] = t.x; c[2 * i + 1][j] = t.y;
        }

    const int gr = blockIdx.y * 128 + ty * 4;
    const int gc = blockIdx.x * 128 + tx * 4;
#pragma unroll
    for (int ih = 0; ih < 2; ih++)
#pragma unroll
        for (int ii = 0; ii < 4; ii++) {
            const int row = gr + ih * 64 + ii;
            const int ci  = ih * 4 + ii;
#pragma unroll
            for (int jh = 0; jh < 2; jh++) {
                const int col = gc + jh * 64;
                float t0 = c[ci][jh * 4 + 0], t1 = c[ci][jh * 4 + 1];
                float t2 = c[ci][jh * 4 + 2], t3 = c[ci][jh * 4 + 3];
                if (EPI == 0) {
                    t0 *= alpha; t1 *= alpha; t2 *= alpha; t3 *= alpha;
                } else {
                    const float4 bv = *(const float4*)(bias + col);
                    t0 += bv.x; t1 += bv.y; t2 += bv.z; t3 += bv.w;
                    if (EPI == 1) {
                        t0 = gelu_exact(t0); t1 = gelu_exact(t1);
                        t2 = gelu_exact(t2); t3 = gelu_exact(t3);
                    }
                }
                *(float4*)(C + (size_t)row * N + col) = make_float4(t0, t1, t2, t3);
            }
        }
}

// ---------------- softmax over rows of [B*S, S] with additive mask[b, k] ----
__global__ void softmax_kernel(float* __restrict__ P, const float* __restrict__ mask) {
    __shared__ float sh[8];
    const int row = blockIdx.x;           // 0..B*S-1
    const int b   = row >> 11;            // S_ = 2048
    float* p = P + (size_t)row * S_;
    const float* m = mask + (size_t)b * S_;
    const int tid = threadIdx.x;          // 256 threads, 8 elems each

    float v[8];
    float mx = -1e30f;
#pragma unroll
    for (int i = 0; i < 8; i++) {
        const int idx = tid + (i << 8);
        v[i] = p[idx] + m[idx];
        mx = fmaxf(mx, v[i]);
    }
    mx = warpMax(mx);
    if ((tid & 31) == 0) sh[tid >> 5] = mx;
    __syncthreads();
    mx = sh[0];
#pragma unroll
    for (int j = 1; j < 8; j++) mx = fmaxf(mx, sh[j]);

    float s = 0.f;
#pragma unroll
    for (int i = 0; i < 8; i++) { v[i] = expf(v[i] - mx); s += v[i]; }
    s = warpSum(s);
    __syncthreads();
    if ((tid & 31) == 0) sh[tid >> 5] = s;
    __syncthreads();
    s = 0.f;
#pragma unroll
    for (int j = 0; j < 8; j++) s += sh[j];
    const float inv = 1.0f / s;
#pragma unroll
    for (int i = 0; i < 8; i++) p[tid + (i << 8)] = v[i] * inv;
}

// ---------------- out = LayerNorm(X + Y) * gamma + beta, rows of D_=1024 ----
__global__ void add_ln_kernel(const float* __restrict__ X, const float* __restrict__ Y,
                              const float* __restrict__ gamma, const float* __restrict__ beta,
                              float* __restrict__ O) {
    __shared__ float shs[8], shq[8];
    const int row = blockIdx.x;
    const int tid = threadIdx.x;          // 256 threads * 4 = 1024
    const size_t base = (size_t)row * D_ + tid * 4;

    const float4 a = *(const float4*)(X + base);
    const float4 b = *(const float4*)(Y + base);
    const float v0 = a.x + b.x, v1 = a.y + b.y, v2 = a.z + b.z, v3 = a.w + b.w;

    float s = v0 + v1 + v2 + v3;
    float q = v0 * v0 + v1 * v1 + v2 * v2 + v3 * v3;
    s = warpSum(s); q = warpSum(q);
    if ((tid & 31) == 0) { shs[tid >> 5] = s; shq[tid >> 5] = q; }
    __syncthreads();
    s = 0.f; q = 0.f;
#pragma unroll
    for (int j = 0; j < 8; j++) { s += shs[j]; q += shq[j]; }
    const float mean = s * (1.0f / D_);
    const float var  = q * (1.0f / D_) - mean * mean;
    const float rstd = rsqrtf(var + 1e-5f);

    const float4 g  = *(const float4*)(gamma + tid * 4);
    const float4 bt = *(const float4*)(beta  + tid * 4);
    float4 o;
    o.x = (v0 - mean) * rstd * g.x + bt.x;
    o.y = (v1 - mean) * rstd * g.y + bt.y;
    o.z = (v2 - mean) * rstd * g.z + bt.z;
    o.w = (v3 - mean) * rstd * g.w + bt.w;
    *(float4*)(O + base) = o;
}

// ---------------- launch ----------------
extern "C" void kernel_launch(void* const* d_in, const int* in_sizes, int n_in,
                              void* d_out, int out_size) {
    const float* h   = (const float*)d_in[0];
    const float* msk = (const float*)d_in[1];
    const float* w1  = (const float*)d_in[2];
    const float* b1  = (const float*)d_in[3];
    const float* w2  = (const float*)d_in[4];
    const float* b2  = (const float*)d_in[5];
    const float* g1  = (const float*)d_in[6];
    const float* be1 = (const float*)d_in[7];
    const float* g2  = (const float*)d_in[8];
    const float* be2 = (const float*)d_in[9];
    float* out = (float*)d_out;

    float *scores, *attn, *x, *y, *f;
    cudaGetSymbolAddress((void**)&scores, g_scores);
    cudaGetSymbolAddress((void**)&attn,   g_attn);
    cudaGetSymbolAddress((void**)&x,      g_x);
    cudaGetSymbolAddress((void**)&y,      g_y);
    cudaGetSymbolAddress((void**)&f,      g_f);

    // 1) scores = (h @ h^T) / sqrt(D)   [B,S,S]
    gemm_kernel<true, 0><<<dim3(S_ / 128, S_ / 128, B_), 256>>>(
        h, h, scores, S_, S_, D_,
        (size_t)S_ * D_, (size_t)S_ * D_, (size_t)S_ * S_, nullptr, 0.03125f);

    // 2) probs = softmax(scores + mask)   (in place)
    softmax_kernel<<<B_ * S_, 256>>>(scores, msk);

    // 3) attn = probs @ h   [B,S,D]
    gemm_kernel<false, 0><<<dim3(D_ / 128, S_ / 128, B_), 256>>>(
        scores, h, attn, S_, D_, S_,
        (size_t)S_ * S_, (size_t)S_ * D_, (size_t)S_ * D_, nullptr, 1.0f);

    // 4) x = LN1(h + attn)
    add_ln_kernel<<<B_ * S_, 256>>>(h, attn, g1, be1, x);

    // 5) y = gelu(x @ w1 + b1)   [B*S, F]
    gemm_kernel<false, 1><<<dim3(F_ / 128, (B_ * S_) / 128, 1), 256>>>(
        x, w1, y, B_ * S_, F_, D_, 0, 0, 0, b1, 1.0f);

    // 6) f = y @ w2 + b2   [B*S, D]
    gemm_kernel<false, 2><<<dim3(D_ / 128, (B_ * S_) / 128, 1), 256>>>(
        y, w2, f, B_ * S_, D_, F_, 0, 0, 0, b2, 1.0f);

    // 7) out = LN2(x + f)
    add_ln_kernel<<<B_ * S_, 256>>>(x, f, g2, be2, out);
}

// round 6
// speedup vs baseline: 2.2666x; 2.2627x over previous
#include <cuda_runtime.h>
#include <math.h>
#include <stdint.h>

#define B_ 4
#define S_ 2048
#define D_ 1024
#define F_ 4096

// ---------------- scratch (device globals: allocation-free) ----------------
__device__ float g_scores[(size_t)B_ * S_ * S_];   //  64 MB (scores -> probs, tf32-rounded)
__device__ float g_attn  [(size_t)B_ * S_ * D_];   //  32 MB
__device__ float g_x     [(size_t)B_ * S_ * D_];   //  32 MB (exact LN1 out)
__device__ float g_xr    [(size_t)B_ * S_ * D_];   //  32 MB (tf32-rounded LN1 out)
__device__ float g_y     [(size_t)B_ * S_ * F_];   // 128 MB (tf32-rounded gelu out)
__device__ float g_f     [(size_t)B_ * S_ * D_];   //  32 MB
__device__ float g_hr    [(size_t)B_ * S_ * D_];   //  32 MB (tf32-rounded h)
__device__ float g_w1r   [(size_t)D_ * F_];        //  16 MB
__device__ float g_w2r   [(size_t)F_ * D_];        //  16 MB

// ---------------- helpers ----------------
__device__ __forceinline__ float tf32r(float x) {
    // round-to-nearest tf32 (unbiased) returned as an fp32 with zeroed low mantissa
    uint32_t u;
    asm("cvt.rna.tf32.f32 %0, %1;" : "=r"(u) : "f"(x));
    return __uint_as_float(u);
}
__device__ __forceinline__ float gelu_exact(float x) {
    return 0.5f * x * (1.0f + erff(x * 0.7071067811865476f));
}
__device__ __forceinline__ float warpSum(float v) {
#pragma unroll
    for (int o = 16; o; o >>= 1) v += __shfl_xor_sync(0xffffffffu, v, o);
    return v;
}
__device__ __forceinline__ float warpMax(float v) {
#pragma unroll
    for (int o = 16; o; o >>= 1) v = fmaxf(v, __shfl_xor_sync(0xffffffffu, v, o));
    return v;
}
__device__ __forceinline__ void mma8(float* c, const uint32_t* a, uint32_t b0, uint32_t b1) {
    asm volatile(
        "mma.sync.aligned.m16n8k8.row.col.f32.tf32.tf32.f32 "
        "{%0,%1,%2,%3}, {%4,%5,%6,%7}, {%8,%9}, {%0,%1,%2,%3};"
        : "+f"(c[0]), "+f"(c[1]), "+f"(c[2]), "+f"(c[3])
        : "r"(a[0]), "r"(a[1]), "r"(a[2]), "r"(a[3]), "r"(b0), "r"(b1));
}

// ---------------- tf32 rounding pass ----------------
__global__ void round_kernel(const float* __restrict__ src, float* __restrict__ dst, int n4) {
    int i = blockIdx.x * blockDim.x + threadIdx.x;
    if (i < n4) {
        float4 v = ((const float4*)src)[i];
        v.x = tf32r(v.x); v.y = tf32r(v.y); v.z = tf32r(v.z); v.w = tf32r(v.w);
        ((float4*)dst)[i] = v;
    }
}

// ---------------- TF32 tensor-core GEMM: C = epi(A @ B) ----------------
// A: [M,K] row-major (pre-rounded to tf32). B: BT ? [N,K] : [K,N] row-major (pre-rounded).
// Block 128x128x32, 256 threads, 8 warps of 64x32, mma.m16n8k8.
// EPI: 0 -> C = acc*alpha ; 1 -> C = tf32r(gelu(acc + bias)) ; 2 -> C = acc + bias
template <bool BT, int EPI>
__global__ void __launch_bounds__(256, 2)
mma_gemm(const float* __restrict__ A, const float* __restrict__ B,
         float* __restrict__ C, int M, int N, int K,
         size_t sA, size_t sB, size_t sC,
         const float* __restrict__ bias, float alpha) {
    __shared__ float As[128 * 36];     // As[m][k], stride 36 (conflict-free frag reads)
    __shared__ float Bs[128 * 36];     // BT: Bs[n][k] stride 36 ; NN: Bs[k][n] stride 136

    A += (size_t)blockIdx.z * sA;
    B += (size_t)blockIdx.z * sB;
    C += (size_t)blockIdx.z * sC;

    const int tid  = threadIdx.x;
    const int lane = tid & 31, warp = tid >> 5;
    const int wm = warp >> 2, wn = warp & 3;     // 2 x 4 warp grid
    const int g = lane >> 2, tig = lane & 3;

    // global load mappings
    const int arow = tid >> 1, acol = (tid & 1) * 16;
    const float* Ag = A + (size_t)(blockIdx.y * 128 + arow) * K + acol;
    int brow, bcol;
    const float* Bg;
    if (BT) { brow = tid >> 1; bcol = (tid & 1) * 16;
              Bg = B + (size_t)(blockIdx.x * 128 + brow) * K + bcol; }
    else    { brow = tid >> 3; bcol = tid & 7;
              Bg = B + (size_t)brow * N + blockIdx.x * 128 + bcol * 4; }

    float4 pa[4], pb[4];
#pragma unroll
    for (int j = 0; j < 4; j++) pa[j] = *(const float4*)(Ag + 4 * j);
    if (BT) {
#pragma unroll
        for (int j = 0; j < 4; j++) pb[j] = *(const float4*)(Bg + 4 * j);
    } else {
#pragma unroll
        for (int j = 0; j < 4; j++) pb[j] = *(const float4*)(Bg + 32 * j);
    }
#pragma unroll
    for (int j = 0; j < 4; j++) *(float4*)(As + arow * 36 + acol + 4 * j) = pa[j];
    if (BT) {
#pragma unroll
        for (int j = 0; j < 4; j++) *(float4*)(Bs + brow * 36 + bcol + 4 * j) = pb[j];
    } else {
#pragma unroll
        for (int j = 0; j < 4; j++) *(float4*)(Bs + brow * 136 + bcol * 4 + 32 * j) = pb[j];
    }
    __syncthreads();

    float acc[4][4][4];
#pragma unroll
    for (int i = 0; i < 4; i++)
#pragma unroll
        for (int j = 0; j < 4; j++)
#pragma unroll
            for (int p = 0; p < 4; p++) acc[i][j][p] = 0.f;

    const uint32_t* Asu = (const uint32_t*)As;
    const uint32_t* Bsu = (const uint32_t*)Bs;
    const int nch = K >> 5;

    for (int ch = 0;; ch++) {
        const bool notlast = (ch + 1 < nch);
        if (notlast) {
            Ag += 32;
#pragma unroll
            for (int j = 0; j < 4; j++) pa[j] = *(const float4*)(Ag + 4 * j);
            if (BT) {
                Bg += 32;
#pragma unroll
                for (int j = 0; j < 4; j++) pb[j] = *(const float4*)(Bg + 4 * j);
            } else {
                Bg += (size_t)32 * N;
#pragma unroll
                for (int j = 0; j < 4; j++) pb[j] = *(const float4*)(Bg + 32 * j);
            }
        }

        // ---- compute 4 k-steps over current tile ----
#pragma unroll
        for (int ks = 0; ks < 4; ks++) {
            uint32_t a[4][4];
#pragma unroll
            for (int mt = 0; mt < 4; mt++) {
                const int r = wm * 64 + mt * 16 + g;
                const int c = ks * 8 + tig;
                a[mt][0] = Asu[r * 36 + c];
                a[mt][1] = Asu[(r + 8) * 36 + c];
                a[mt][2] = Asu[r * 36 + c + 4];
                a[mt][3] = Asu[(r + 8) * 36 + c + 4];
            }
#pragma unroll
            for (int nt = 0; nt < 4; nt++) {
                const int n = wn * 32 + nt * 8 + g;
                uint32_t b0, b1;
                if (BT) {
                    b0 = Bsu[n * 36 + ks * 8 + tig];
                    b1 = Bsu[n * 36 + ks * 8 + tig + 4];
                } else {
                    b0 = Bsu[(ks * 8 + tig) * 136 + n];
                    b1 = Bsu[(ks * 8 + tig + 4) * 136 + n];
                }
#pragma unroll
                for (int mt = 0; mt < 4; mt++) mma8(acc[mt][nt], a[mt], b0, b1);
            }
        }

        if (!notlast) break;
        __syncthreads();
#pragma unroll
        for (int j = 0; j < 4; j++) *(float4*)(As + arow * 36 + acol + 4 * j) = pa[j];
        if (BT) {
#pragma unroll
            for (int j = 0; j < 4; j++) *(float4*)(Bs + brow * 36 + bcol + 4 * j) = pb[j];
        } else {
#pragma unroll
            for (int j = 0; j < 4; j++) *(float4*)(Bs + brow * 136 + bcol * 4 + 32 * j) = pb[j];
        }
        __syncthreads();
    }

    // ---- epilogue ----
#pragma unroll
    for (int mt = 0; mt < 4; mt++) {
        const int r0 = blockIdx.y * 128 + wm * 64 + mt * 16 + g;
#pragma unroll
        for (int nt = 0; nt < 4; nt++) {
            const int c0 = blockIdx.x * 128 + wn * 32 + nt * 8 + 2 * tig;
            float v0 = acc[mt][nt][0], v1 = acc[mt][nt][1];
            float v2 = acc[mt][nt][2], v3 = acc[mt][nt][3];
            if (EPI == 0) {
                v0 *= alpha; v1 *= alpha; v2 *= alpha; v3 *= alpha;
            } else {
                const float bb0 = bias[c0], bb1 = bias[c0 + 1];
                v0 += bb0; v1 += bb1; v2 += bb0; v3 += bb1;
                if (EPI == 1) {
                    v0 = tf32r(gelu_exact(v0)); v1 = tf32r(gelu_exact(v1));
                    v2 = tf32r(gelu_exact(v2)); v3 = tf32r(gelu_exact(v3));
                }
            }
            *(float2*)(C + (size_t)r0 * N + c0)       = make_float2(v0, v1);
            *(float2*)(C + (size_t)(r0 + 8) * N + c0) = make_float2(v2, v3);
        }
    }
}

// ---------------- softmax over rows of [B*S, S] with additive mask[b, k] ----
// writes tf32-rounded probs (consumed as mma A operand)
__global__ void softmax_kernel(float* __restrict__ P, const float* __restrict__ mask) {
    __shared__ float sh[8];
    const int row = blockIdx.x;
    const int b   = row >> 11;
    float* p = P + (size_t)row * S_;
    const float* m = mask + (size_t)b * S_;
    const int tid = threadIdx.x;

    float v[8];
    float mx = -1e30f;
#pragma unroll
    for (int i = 0; i < 8; i++) {
        const int idx = tid + (i << 8);
        v[i] = p[idx] + m[idx];
        mx = fmaxf(mx, v[i]);
    }
    mx = warpMax(mx);
    if ((tid & 31) == 0) sh[tid >> 5] = mx;
    __syncthreads();
    mx = sh[0];
#pragma unroll
    for (int j = 1; j < 8; j++) mx = fmaxf(mx, sh[j]);

    float s = 0.f;
#pragma unroll
    for (int i = 0; i < 8; i++) { v[i] = expf(v[i] - mx); s += v[i]; }
    s = warpSum(s);
    __syncthreads();
    if ((tid & 31) == 0) sh[tid >> 5] = s;
    __syncthreads();
    s = 0.f;
#pragma unroll
    for (int j = 0; j < 8; j++) s += sh[j];
    const float inv = 1.0f / s;
#pragma unroll
    for (int i = 0; i < 8; i++) p[tid + (i << 8)] = tf32r(v[i] * inv);
}

// ---------------- out = LayerNorm(X + Y); optionally also tf32-rounded copy ----
template <bool WR>
__global__ void add_ln_kernel(const float* __restrict__ X, const float* __restrict__ Y,
                              const float* __restrict__ gamma, const float* __restrict__ beta,
                              float* __restrict__ O, float* __restrict__ OR_) {
    __shared__ float shs[8], shq[8];
    const int row = blockIdx.x;
    const int tid = threadIdx.x;
    const size_t base = (size_t)row * D_ + tid * 4;

    const float4 a = *(const float4*)(X + base);
    const float4 b = *(const float4*)(Y + base);
    const float v0 = a.x + b.x, v1 = a.y + b.y, v2 = a.z + b.z, v3 = a.w + b.w;

    float s = v0 + v1 + v2 + v3;
    float q = v0 * v0 + v1 * v1 + v2 * v2 + v3 * v3;
    s = warpSum(s); q = warpSum(q);
    if ((tid & 31) == 0) { shs[tid >> 5] = s; shq[tid >> 5] = q; }
    __syncthreads();
    s = 0.f; q = 0.f;
#pragma unroll
    for (int j = 0; j < 8; j++) { s += shs[j]; q += shq[j]; }
    const float mean = s * (1.0f / D_);
    const float var  = q * (1.0f / D_) - mean * mean;
    const float rstd = rsqrtf(var + 1e-5f);

    const float4 gm = *(const float4*)(gamma + tid * 4);
    const float4 bt = *(const float4*)(beta  + tid * 4);
    float4 o;
    o.x = (v0 - mean) * rstd * gm.x + bt.x;
    o.y = (v1 - mean) * rstd * gm.y + bt.y;
    o.z = (v2 - mean) * rstd * gm.z + bt.z;
    o.w = (v3 - mean) * rstd * gm.w + bt.w;
    *(float4*)(O + base) = o;
    if (WR) {
        float4 r;
        r.x = tf32r(o.x); r.y = tf32r(o.y); r.z = tf32r(o.z); r.w = tf32r(o.w);
        *(float4*)(OR_ + base) = r;
    }
}

// ---------------- launch ----------------
extern "C" void kernel_launch(void* const* d_in, const int* in_sizes, int n_in,
                              void* d_out, int out_size) {
    const float* h   = (const float*)d_in[0];
    const float* msk = (const float*)d_in[1];
    const float* w1  = (const float*)d_in[2];
    const float* b1  = (const float*)d_in[3];
    const float* w2  = (const float*)d_in[4];
    const float* b2  = (const float*)d_in[5];
    const float* g1  = (const float*)d_in[6];
    const float* be1 = (const float*)d_in[7];
    const float* g2  = (const float*)d_in[8];
    const float* be2 = (const float*)d_in[9];
    float* out = (float*)d_out;

    float *scores, *attn, *x, *xr, *y, *f, *hr, *w1r, *w2r;
    cudaGetSymbolAddress((void**)&scores, g_scores);
    cudaGetSymbolAddress((void**)&attn,   g_attn);
    cudaGetSymbolAddress((void**)&x,      g_x);
    cudaGetSymbolAddress((void**)&xr,     g_xr);
    cudaGetSymbolAddress((void**)&y,      g_y);
    cudaGetSymbolAddress((void**)&f,      g_f);
    cudaGetSymbolAddress((void**)&hr,     g_hr);
    cudaGetSymbolAddress((void**)&w1r,    g_w1r);
    cudaGetSymbolAddress((void**)&w2r,    g_w2r);

    // 0) tf32-round constants/inputs
    round_kernel<<<(B_ * S_ * D_ / 4 + 255) / 256, 256>>>(h,  hr,  B_ * S_ * D_ / 4);
    round_kernel<<<(D_ * F_ / 4 + 255) / 256, 256>>>(w1, w1r, D_ * F_ / 4);
    round_kernel<<<(F_ * D_ / 4 + 255) / 256, 256>>>(w2, w2r, F_ * D_ / 4);

    // 1) scores = (h @ h^T) / sqrt(D)
    mma_gemm<true, 0><<<dim3(S_ / 128, S_ / 128, B_), 256>>>(
        hr, hr, scores, S_, S_, D_,
        (size_t)S_ * D_, (size_t)S_ * D_, (size_t)S_ * S_, nullptr, 0.03125f);

    // 2) probs = tf32r(softmax(scores + mask))  (in place)
    softmax_kernel<<<B_ * S_, 256>>>(scores, msk);

    // 3) attn = probs @ h
    mma_gemm<false, 0><<<dim3(D_ / 128, S_ / 128, B_), 256>>>(
        scores, hr, attn, S_, D_, S_,
        (size_t)S_ * S_, (size_t)S_ * D_, (size_t)S_ * D_, nullptr, 1.0f);

    // 4) x = LN1(h + attn)  (+ tf32 copy)
    add_ln_kernel<true><<<B_ * S_, 256>>>(h, attn, g1, be1, x, xr);

    // 5) y = tf32r(gelu(x @ w1 + b1))
    mma_gemm<false, 1><<<dim3(F_ / 128, (B_ * S_) / 128, 1), 256>>>(
        xr, w1r, y, B_ * S_, F_, D_, 0, 0, 0, b1, 1.0f);

    // 6) f = y @ w2 + b2
    mma_gemm<false, 2><<<dim3(D_ / 128, (B_ * S_) / 128, 1), 256>>>(
        y, w2r, f, B_ * S_, D_, F_, 0, 0, 0, b2, 1.0f);

    // 7) out = LN2(x + f)
    add_ln_kernel<false><<<B_ * S_, 256>>>(x, f, g2, be2, out, nullptr);
}